// round 4
// baseline (speedup 1.0000x reference)
#include <cuda_runtime.h>

// Detail_loss: loss = (mean|conv(dx,kh)| + mean|conv(dx,kv)|)/2 with dx=infer-ref
// and fixed [-0.5,0,0.5] gradient kernels broadcast over 3x3 channel pairs.
// Reduces to: S = sum_c(infer-ref); accumulate |S[h,w+1]-S[h,w-1]| + |S[h+1,w]-S[h-1,w]|
// over all pixels (zero padding), scaled by 1/(4 * N * 258 * 256).
// Single fused kernel: per-block partial -> arrival counter -> last block reduces.

#define H 256
#define W 256
#define C 3
#define RSTRIP 32              // image rows per block
#define SHROWS (RSTRIP + 2)    // +1 halo row top/bottom (34)
#define STRIPS (H / RSTRIP)    // 8
#define MAXBLK 1024

__device__ float        g_partials[MAXBLK];
__device__ unsigned int g_count = 0;   // self-resetting arrival counter

__device__ __forceinline__ void load_task(
    float (*S)[W], const float* __restrict__ infer, const float* __restrict__ ref,
    size_t base, int row0, int idx)
{
    const int r  = idx >> 6;            // shared row 0..33
    const int c4 = (idx & 63) << 2;     // column (float4 granularity)
    const int g  = row0 + r;            // global image row
    float4 v = make_float4(0.f, 0.f, 0.f, 0.f);
    if ((unsigned)g < (unsigned)H) {
        const size_t off = base + (size_t)g * W + c4;
        #pragma unroll
        for (int ch = 0; ch < C; ch++) {
            const float4 a  = __ldg((const float4*)(infer + off + (size_t)ch * (H * W)));
            const float4 bb = __ldg((const float4*)(ref   + off + (size_t)ch * (H * W)));
            v.x += a.x - bb.x;
            v.y += a.y - bb.y;
            v.z += a.z - bb.z;
            v.w += a.w - bb.w;
        }
    }
    *(float4*)&S[r][c4] = v;
}

__global__ __launch_bounds__(256, 6)
void dl_fused(const float* __restrict__ infer, const float* __restrict__ ref,
              float* __restrict__ out, int n_img)
{
    __shared__ float  S[SHROWS][W];
    __shared__ float  wsum[8];
    __shared__ double dsum[8];
    __shared__ bool   is_last;

    const int bid  = blockIdx.x;
    const int n    = bid >> 3;          // image index
    const int s    = bid & 7;           // strip index
    const int row0 = s * RSTRIP - 1;    // global row of shared row 0
    const size_t base = (size_t)n * (C * H * W);
    const int tid = threadIdx.x;

    // ---- Phase 1: build channel-summed diff tile (34 rows x 256 cols) ----
    // 34*64 = 2176 float4 tasks; 8 full rounds of 256 + predicated tail of 128.
    #pragma unroll 4
    for (int k = 0; k < 8; k++)
        load_task(S, infer, ref, base, row0, tid + k * 256);
    if (tid < 128)
        load_task(S, infer, ref, base, row0, tid + 2048);
    __syncthreads();

    // ---- Phase 2: 8-row x 4-col patch per thread, rolling float4 window ----
    const int g  = tid >> 6;        // row group 0..3
    const int x  = tid & 63;        // col group 0..63
    const int c4 = x << 2;
    const int r0 = g * 8;           // shared-row base of this group's window

    float4 a  = *(const float4*)&S[r0][c4];
    float4 bv = *(const float4*)&S[r0 + 1][c4];
    float acc = 0.f;
    #pragma unroll
    for (int i = 0; i < 8; i++) {
        const int rr = r0 + 1 + i;
        const float4 cv   = *(const float4*)&S[rr + 1][c4];
        const float left  = (x > 0)  ? S[rr][c4 - 1] : 0.f;
        const float right = (x < 63) ? S[rr][c4 + 4] : 0.f;
        // horizontal: |S[rr][j+1]-S[rr][j-1]| for j = c4..c4+3
        acc += fabsf(bv.y - left);
        acc += fabsf(bv.z - bv.x);
        acc += fabsf(bv.w - bv.y);
        acc += fabsf(right - bv.z);
        // vertical: |S[rr+1][j]-S[rr-1][j]|
        acc += fabsf(cv.x - a.x);
        acc += fabsf(cv.y - a.y);
        acc += fabsf(cv.z - a.z);
        acc += fabsf(cv.w - a.w);
        a = bv; bv = cv;
    }

    // ---- Block reduction ----
    #pragma unroll
    for (int o = 16; o; o >>= 1) acc += __shfl_down_sync(0xffffffffu, acc, o);
    if ((tid & 31) == 0) wsum[tid >> 5] = acc;
    __syncthreads();
    if (tid == 0) {
        float t = 0.f;
        #pragma unroll
        for (int i = 0; i < 8; i++) t += wsum[i];
        g_partials[bid] = t;
        __threadfence();                      // make partial visible (release)
        unsigned old = atomicAdd(&g_count, 1u);
        is_last = (old == (unsigned)gridDim.x - 1u);
    }
    __syncthreads();

    // ---- Last block: final reduction over all partials ----
    if (is_last) {
        const int nb = gridDim.x;
        double d = 0.0;
        for (int i = tid; i < nb; i += 256)
            d += (double)((volatile float*)g_partials)[i];
        #pragma unroll
        for (int o = 16; o; o >>= 1) d += __shfl_down_sync(0xffffffffu, d, o);
        if ((tid & 31) == 0) dsum[tid >> 5] = d;
        __syncthreads();
        if (tid == 0) {
            double t = 0.0;
            #pragma unroll
            for (int i = 0; i < 8; i++) t += dsum[i];
            out[0] = (float)(t / (4.0 * (double)n_img * 258.0 * 256.0));
            g_count = 0;                       // reset for next graph replay
        }
    }
}

extern "C" void kernel_launch(void* const* d_in, const int* in_sizes, int n_in,
                              void* d_out, int out_size) {
    const float* infer = (const float*)d_in[0];
    const float* ref   = (const float*)d_in[1];
    const int n_img = in_sizes[0] / (C * H * W);   // 2*7*7 = 98
    dl_fused<<<n_img * STRIPS, 256>>>(infer, ref, (float*)d_out, n_img);
}

// round 5
// speedup vs baseline: 1.4991x; 1.4991x over previous
#include <cuda_runtime.h>

// Detail_loss: loss = (mean|conv(dx,kh)| + mean|conv(dx,kv)|)/2, dx=infer-ref,
// fixed [-0.5,0,0.5] kernels broadcast over 3x3 channel pairs.
// Reduces to S = sum_c(infer-ref); accumulate |S[h,w+1]-S[h,w-1]| + |S[h+1,w]-S[h-1,w]|
// (zero pad), scaled by 1/(4 * N * 258 * 256).
//
// Smem-free streaming: each warp owns a 16-row x 128-col strip. Rolling 3-row
// float4 window in registers for vertical grads; warp shuffles + scalar halo
// loads for horizontal grads. Single fused kernel, single wave, one atomic/block.

#define H 256
#define W 256
#define C 3
#define RSTRIP 16
#define IMG (C * H * W)

__device__ double       g_acc   = 0.0;
__device__ unsigned int g_count = 0;

__device__ __forceinline__ float4 loadS4(const float* __restrict__ pi,
                                         const float* __restrict__ pr, int r) {
    const size_t ro = (size_t)r * W;
    float4 v = make_float4(0.f, 0.f, 0.f, 0.f);
    #pragma unroll
    for (int ch = 0; ch < C; ch++) {
        const size_t o = ro + (size_t)ch * (H * W);
        const float4 a = __ldg((const float4*)(pi + o));
        const float4 b = __ldg((const float4*)(pr + o));
        v.x += a.x - b.x; v.y += a.y - b.y;
        v.z += a.z - b.z; v.w += a.w - b.w;
    }
    return v;
}

__device__ __forceinline__ float loadS1(const float* __restrict__ pi,
                                        const float* __restrict__ pr, int r) {
    const size_t ro = (size_t)r * W;
    float v = 0.f;
    #pragma unroll
    for (int ch = 0; ch < C; ch++) {
        const size_t o = ro + (size_t)ch * (H * W);
        v += __ldg(pi + o) - __ldg(pr + o);
    }
    return v;
}

__global__ __launch_bounds__(256)
void dl_fused(const float* __restrict__ infer, const float* __restrict__ ref,
              float* __restrict__ out, int n_img)
{
    const int tid  = threadIdx.x;
    const int lane = tid & 31;
    const int wid  = tid >> 5;
    const int gw   = blockIdx.x * 8 + wid;   // global warp id = strip id
    const int n    = gw >> 5;                // image (32 strips per image)
    const int rem  = gw & 31;
    const int seg  = rem & 1;                // column segment 0/1
    const int rs   = rem >> 1;               // row strip 0..15
    const int r0   = rs * RSTRIP;
    const int c0   = seg * 128;
    const int col  = c0 + lane * 4;

    const float* pi = infer + (size_t)n * IMG + col;
    const float* pr = ref   + (size_t)n * IMG + col;

    // Halo column: lane 0 needs S[.,c0-1]; lane 31 needs S[.,c0+128].
    const bool wantHalo = (lane == 0) ? (c0 > 0)
                        : ((lane == 31) && (c0 + 128 < W));
    const int hoff = ((lane == 0) ? -1 : 128) - lane * 4;  // relative to col
    const float* hi = pi + hoff;
    const float* hr = pr + hoff;

    float4 a  = (r0 > 0) ? loadS4(pi, pr, r0 - 1) : make_float4(0.f, 0.f, 0.f, 0.f);
    float4 b  = loadS4(pi, pr, r0);
    float  bh = wantHalo ? loadS1(hi, hr, r0) : 0.f;

    float acc = 0.f;
    #pragma unroll 2
    for (int i = 0; i < RSTRIP; i++) {
        const int r = r0 + i;
        float4 c  = make_float4(0.f, 0.f, 0.f, 0.f);
        float  chv = 0.f;
        if (r + 1 < H) {
            c = loadS4(pi, pr, r + 1);
            if (wantHalo) chv = loadS1(hi, hr, r + 1);
        }
        // horizontal gradients of row r (factor-2 grads; scaled at the end)
        float lf = __shfl_up_sync(0xffffffffu, b.w, 1);
        float rt = __shfl_down_sync(0xffffffffu, b.x, 1);
        if (lane == 0)  lf = bh;   // left halo (0 at image edge)
        if (lane == 31) rt = bh;   // right halo (0 at image edge)
        acc += fabsf(b.y - lf) + fabsf(b.z - b.x)
             + fabsf(b.w - b.y) + fabsf(rt  - b.z);
        // vertical gradients of row r
        acc += fabsf(c.x - a.x) + fabsf(c.y - a.y)
             + fabsf(c.z - a.z) + fabsf(c.w - a.w);
        a = b; b = c; bh = chv;
    }

    // ---- warp + block reduction ----
    #pragma unroll
    for (int o = 16; o; o >>= 1) acc += __shfl_down_sync(0xffffffffu, acc, o);
    __shared__ float wsum[8];
    if (lane == 0) wsum[wid] = acc;
    __syncthreads();
    if (tid == 0) {
        float t = 0.f;
        #pragma unroll
        for (int i = 0; i < 8; i++) t += wsum[i];
        atomicAdd(&g_acc, (double)t);
        __threadfence();
        const unsigned old = atomicAdd(&g_count, 1u);
        if (old == gridDim.x - 1u) {            // last block finalizes
            __threadfence();
            const double s = atomicAdd(&g_acc, 0.0);  // coherent read
            out[0] = (float)(s / (4.0 * (double)n_img * 258.0 * 256.0));
            g_acc   = 0.0;                      // reset for next graph replay
            g_count = 0u;
        }
    }
}

extern "C" void kernel_launch(void* const* d_in, const int* in_sizes, int n_in,
                              void* d_out, int out_size) {
    const float* infer = (const float*)d_in[0];
    const float* ref   = (const float*)d_in[1];
    const int n_img = in_sizes[0] / IMG;               // 2*7*7 = 98
    const int nblk  = n_img * 32 / 8;                  // 392
    dl_fused<<<nblk, 256>>>(infer, ref, (float*)d_out, n_img);
}